// round 3
// baseline (speedup 1.0000x reference)
#include <cuda_runtime.h>
#include <cuda_bf16.h>

#define NMAX 50000
#define EMAX 800000
#define F 128
#define EFD 6

#define PREP_BLOCKS 148
#define PREP_T 512

// ---------------- device scratch ----------------
__device__ int    g_is64;
__device__ int    g_counts[NMAX];
__device__ int    g_cursor[NMAX];
__device__ int    g_rowptr[NMAX + 1];
__device__ int    g_src[EMAX];
__device__ int    g_dst[EMAX];
__device__ int2   g_edges[EMAX];
__device__ float4 g_aggX[NMAX * (F / 4)];
__device__ float  g_aggE[NMAX * EFD];
__device__ int    g_blocksum[256];
__device__ int    g_blockoff[256];
__device__ int    g_bar[5];   // software grid barriers (zero at first launch)

// ---------------- software grid barrier -------------------------------------
__device__ __forceinline__ void grid_barrier(int id) {
    __syncthreads();
    if (threadIdx.x == 0) {
        __threadfence();                       // release block's writes
        atomicAdd(&g_bar[id], 1);
        const volatile int* vb = g_bar;
        while (vb[id] < PREP_BLOCKS) { }
        __threadfence();                       // acquire
    }
    __syncthreads();
}

// ---------------- fused prep: zero+detect | hist | scan | scatter ------------
__global__ void __launch_bounds__(PREP_T)
k_prep(const void* __restrict__ ei, int N, int E) {
    const int tid  = blockIdx.x * PREP_T + threadIdx.x;
    const int nth  = PREP_BLOCKS * PREP_T;
    const int lane = threadIdx.x & 31;
    const int T    = (N + 255) >> 8;           // #tiles of 256

    // ---- P0: zero counts, detect index width, reset bar[4] from prior replay
    if (blockIdx.x == 0 && threadIdx.x == 0) {
        const long long* p = (const long long*)ei;
        int ok = 1;
        int lim = E < 128 ? E : 128;
        for (int j = 0; j < lim; j++) {
            long long v = p[j];
            if (v < 0 || v >= (long long)N) { ok = 0; break; }
        }
        g_is64 = ok;
        atomicExch(&g_bar[4], 0);
    }
    for (int i = tid; i < N; i += nth) g_counts[i] = 0;
    grid_barrier(0);

    // ---- P1: decode + histogram (atomics bypass L1)
    const int is64 = __ldcg(&g_is64);
    if (is64) {
        const longlong2* p = (const longlong2*)ei;
        for (int e = tid; e < E; e += nth) {
            longlong2 v = p[e];
            int s = (int)v.x, d = (int)v.y;
            g_src[e] = s; g_dst[e] = d;
            atomicAdd(&g_counts[d], 1);
        }
    } else {
        const int2* p = (const int2*)ei;
        for (int e = tid; e < E; e += nth) {
            int2 v = p[e];
            g_src[e] = v.x; g_dst[e] = v.y;
            atomicAdd(&g_counts[v.y], 1);
        }
    }
    grid_barrier(1);
    if (blockIdx.x == 0 && threadIdx.x == 0) atomicExch(&g_bar[0], 0);

    // ---- P2: per-tile (256) exclusive scan, one warp per tile
    {
        int gw = tid >> 5;
        int nw = nth >> 5;
        for (int t = gw; t < T; t += nw) {
            int base = t << 8;
            int v[8]; int s = 0;
            #pragma unroll
            for (int j = 0; j < 8; j++) {
                int idx = base + lane * 8 + j;
                int c = (idx < N) ? __ldcg(&g_counts[idx]) : 0;
                v[j] = s; s += c;
            }
            int x = s;
            #pragma unroll
            for (int o = 1; o < 32; o <<= 1) {
                int y = __shfl_up_sync(0xffffffffu, x, o);
                if (lane >= o) x += y;
            }
            int excl = x - s;
            #pragma unroll
            for (int j = 0; j < 8; j++) {
                int idx = base + lane * 8 + j;
                if (idx < N) g_rowptr[idx] = excl + v[j];
            }
            if (lane == 31) g_blocksum[t] = x;
        }
    }
    grid_barrier(2);
    if (blockIdx.x == 0 && threadIdx.x == 0) atomicExch(&g_bar[1], 0);

    // ---- P3: scan of tile sums (block 0, warp 0; 7 per lane covers T<=224)
    if (blockIdx.x == 0 && threadIdx.x < 32) {
        int vals[7]; int s = 0;
        #pragma unroll
        for (int j = 0; j < 7; j++) {
            int idx = lane * 7 + j;
            int v = (idx < T) ? __ldcg(&g_blocksum[idx]) : 0;
            vals[j] = s; s += v;
        }
        int x = s;
        #pragma unroll
        for (int o = 1; o < 32; o <<= 1) {
            int y = __shfl_up_sync(0xffffffffu, x, o);
            if (lane >= o) x += y;
        }
        int excl = x - s;
        #pragma unroll
        for (int j = 0; j < 7; j++) {
            int idx = lane * 7 + j;
            if (idx < T) g_blockoff[idx] = excl + vals[j];
        }
        if (lane == 31) g_rowptr[N] = x;
    }
    grid_barrier(3);
    if (blockIdx.x == 0 && threadIdx.x == 0) atomicExch(&g_bar[2], 0);

    // ---- P4: add tile offsets, init cursor
    for (int i = tid; i < N; i += nth) {
        int r = __ldcg(&g_rowptr[i]) + __ldcg(&g_blockoff[i >> 8]);
        g_rowptr[i] = r;
        g_cursor[i] = r;
    }
    grid_barrier(4);
    if (blockIdx.x == 0 && threadIdx.x == 0) atomicExch(&g_bar[3], 0);

    // ---- P5: scatter edges into CSR slots (MLP=4)
    for (int e0 = tid * 4; e0 < E; e0 += nth * 4) {
        int d[4], s[4];
        #pragma unroll
        for (int j = 0; j < 4; j++) {
            int e = e0 + j;
            if (e < E) { d[j] = __ldcg(&g_dst[e]); s[j] = __ldcg(&g_src[e]); }
        }
        #pragma unroll
        for (int j = 0; j < 4; j++) {
            int e = e0 + j;
            if (e < E) {
                int p = atomicAdd(&g_cursor[d[j]], 1);
                g_edges[p] = make_int2(s[j], e);
            }
        }
    }
    // g_bar[4] reset at next replay's P0.
}

// ---------------- K4: warp-per-node aggregation, 8-deep gather --------------
__global__ void k4_aggregate(const float4* __restrict__ X4,
                             const float* __restrict__ eF, int N) {
    int gwarp = (blockIdx.x * blockDim.x + threadIdx.x) >> 5;
    int lane  = threadIdx.x & 31;
    int nwarp = (gridDim.x * blockDim.x) >> 5;
    for (int v = gwarp; v < N; v += nwarp) {
        int s0 = g_rowptr[v], s1 = g_rowptr[v + 1];
        float4 acc = make_float4(0.f, 0.f, 0.f, 0.f);
        float ae = 0.f;
        for (int base = s0; base < s1; base += 32) {
            int cnt = s1 - base; if (cnt > 32) cnt = 32;
            int2 se = g_edges[base + (lane < cnt ? lane : 0)];
            for (int j = 0; j < cnt; j += 8) {
                #pragma unroll
                for (int u = 0; u < 8; u++) {
                    if (j + u < cnt) {  // uniform across warp
                        int sj = __shfl_sync(0xffffffffu, se.x, j + u);
                        int ej = __shfl_sync(0xffffffffu, se.y, j + u);
                        float4 xv = X4[(long)sj * 32 + lane];
                        acc.x += xv.x; acc.y += xv.y;
                        acc.z += xv.z; acc.w += xv.w;
                        if (lane < EFD) ae += eF[(long)ej * EFD + lane];
                    }
                }
            }
        }
        g_aggX[(long)v * 32 + lane] = acc;
        if (lane < EFD) g_aggE[v * EFD + lane] = ae;
    }
}

// ---------------- K5: fused GEMM + edge-GEMM + bias*deg + relu -------------
#define K5_THREADS 512
#define K5_RPW 8
#define K5_SMEM ((F*F + EFD*F + F) * 4 + (K5_THREADS/32) * K5_RPW * F * 4)

__global__ __launch_bounds__(K5_THREADS)
void k5_final(const float* __restrict__ W, const float* __restrict__ b,
              const float* __restrict__ We, const float* __restrict__ be,
              float* __restrict__ out, int N) {
    extern __shared__ float smem[];
    float*  Ws   = smem;
    float*  Wes  = Ws + F * F;
    float*  bsum = Wes + EFD * F;
    float4* xs   = (float4*)(bsum + F);

    int tid = threadIdx.x;
    for (int i = tid; i < F * F; i += K5_THREADS) Ws[i] = W[i];
    for (int i = tid; i < EFD * F; i += K5_THREADS) Wes[i] = We[i];
    for (int i = tid; i < F; i += K5_THREADS) bsum[i] = b[i] + be[i];
    __syncthreads();

    int warp = tid >> 5, lane = tid & 31;
    float4* xw4 = xs + warp * (K5_RPW * 32);
    const float* xw = (const float*)xw4;

    int nGroups = (N + K5_RPW - 1) / K5_RPW;
    for (int g = blockIdx.x * (K5_THREADS / 32) + warp; g < nGroups;
         g += gridDim.x * (K5_THREADS / 32)) {
        int row0 = g * K5_RPW;
        int nr = N - row0; if (nr > K5_RPW) nr = K5_RPW;
        #pragma unroll
        for (int r = 0; r < K5_RPW; r++) {
            int row = row0 + (r < nr ? r : 0);
            xw4[r * 32 + lane] = g_aggX[(long)row * 32 + lane];
        }
        __syncwarp();

        float4 acc[K5_RPW];
        #pragma unroll
        for (int r = 0; r < K5_RPW; r++) acc[r] = make_float4(0.f, 0.f, 0.f, 0.f);

        #pragma unroll 2
        for (int k = 0; k < F; k += 4) {
            float4 xv[K5_RPW];
            #pragma unroll
            for (int r = 0; r < K5_RPW; r++)
                xv[r] = *(const float4*)(xw + (r << 7) + k);
            #pragma unroll
            for (int kk = 0; kk < 4; kk++) {
                float4 w4 = ((const float4*)(Ws + ((k + kk) << 7)))[lane];
                #pragma unroll
                for (int r = 0; r < K5_RPW; r++) {
                    float xk = (kk == 0) ? xv[r].x : (kk == 1) ? xv[r].y
                             : (kk == 2) ? xv[r].z : xv[r].w;
                    acc[r].x = fmaf(xk, w4.x, acc[r].x);
                    acc[r].y = fmaf(xk, w4.y, acc[r].y);
                    acc[r].z = fmaf(xk, w4.z, acc[r].z);
                    acc[r].w = fmaf(xk, w4.w, acc[r].w);
                }
            }
        }

        float4 b4 = ((const float4*)bsum)[lane];
        for (int r = 0; r < nr; r++) {
            int row = row0 + r;
            float deg = (float)(g_rowptr[row + 1] - g_rowptr[row]);
            float4 o = acc[r];
            o.x = fmaf(deg, b4.x, o.x);
            o.y = fmaf(deg, b4.y, o.y);
            o.z = fmaf(deg, b4.z, o.z);
            o.w = fmaf(deg, b4.w, o.w);
            #pragma unroll
            for (int k = 0; k < EFD; k++) {
                float ek = g_aggE[row * EFD + k];
                float4 w4 = ((const float4*)(Wes + (k << 7)))[lane];
                o.x = fmaf(ek, w4.x, o.x);
                o.y = fmaf(ek, w4.y, o.y);
                o.z = fmaf(ek, w4.z, o.z);
                o.w = fmaf(ek, w4.w, o.w);
            }
            o.x = fmaxf(o.x, 0.f); o.y = fmaxf(o.y, 0.f);
            o.z = fmaxf(o.z, 0.f); o.w = fmaxf(o.w, 0.f);
            ((float4*)out)[(long)row * 32 + lane] = o;
        }
        __syncwarp();
    }
}

// ---------------------------------------------------------------------------
extern "C" void kernel_launch(void* const* d_in, const int* in_sizes, int n_in,
                              void* d_out, int out_size) {
    const float* X  = (const float*)d_in[0];
    const void*  EI = d_in[1];
    const float* EF = (const float*)d_in[2];
    const float* W  = (const float*)d_in[3];
    const float* b  = (const float*)d_in[4];
    const float* We = (const float*)d_in[5];
    const float* be = (const float*)d_in[6];
    float* out = (float*)d_out;

    int N = in_sizes[0] / F;
    int E = in_sizes[2] / EFD;

    cudaFuncSetAttribute(k5_final, cudaFuncAttributeMaxDynamicSharedMemorySize,
                         K5_SMEM);

    k_prep<<<PREP_BLOCKS, PREP_T>>>(EI, N, E);
    k4_aggregate<<<(N * 32 + 255) / 256, 256>>>((const float4*)X, EF, N);
    k5_final<<<148, K5_THREADS, K5_SMEM>>>(W, b, We, be, out, N);
}